// round 2
// baseline (speedup 1.0000x reference)
#include <cuda_runtime.h>
#include <mma.h>
#include <math.h>

using namespace nvcuda;

#define TOKENS 8192
#define NEXP   64
#define TOPK   8
#define HID    2048
#define INTER  768

#define BM 128
#define BN 64
#define BK 32

// Max padded rows: 65536 + 64 * (BM-1) rounded up
#define MAXROWS (TOKENS * TOPK + NEXP * BM)   // 73728

// ---------------- scratch (static device memory; no allocations) ----------------
__device__ float g_h[(size_t)MAXROWS * INTER];     // silu(gate)*up, per expanded row
__device__ float g_down[(size_t)MAXROWS * HID];    // down-proj result per expanded row
__device__ int   g_row_src[MAXROWS];               // slot -> source token
__device__ int   g_slot_of[TOKENS * TOPK];         // (t,k) -> slot
__device__ float g_wt[TOKENS * TOPK];              // routing weight per (t,k)
__device__ int   g_expert[TOKENS * TOPK];          // expert id per (t,k)
__device__ int   g_cnt[NEXP];
__device__ int   g_cursor[NEXP];
__device__ int   g_off[NEXP + 1];                  // padded group offsets

// ---------------- 1. zero counters ----------------
__global__ void k_zero() {
    int i = threadIdx.x;
    if (i < NEXP) { g_cnt[i] = 0; g_cursor[i] = 0; }
}

// ---------------- 2. routing: top-8 + softmax + histogram ----------------
__global__ void k_route(const float* __restrict__ logits) {
    int t = blockIdx.x * blockDim.x + threadIdx.x;
    if (t >= TOKENS) return;
    float l[NEXP];
#pragma unroll
    for (int i = 0; i < NEXP; i++) l[i] = logits[t * NEXP + i];

    float vals[TOPK]; int ids[TOPK];
#pragma unroll
    for (int k = 0; k < TOPK; k++) {
        float best = -INFINITY; int bi = 0;
#pragma unroll
        for (int i = 0; i < NEXP; i++) {
            if (l[i] > best) { best = l[i]; bi = i; }
        }
        vals[k] = best; ids[k] = bi;
        l[bi] = -INFINITY;
    }
    float m = vals[0];
    float ex[TOPK]; float s = 0.f;
#pragma unroll
    for (int k = 0; k < TOPK; k++) { ex[k] = expf(vals[k] - m); s += ex[k]; }
    float inv = 1.f / s;
#pragma unroll
    for (int k = 0; k < TOPK; k++) {
        g_wt[t * TOPK + k] = ex[k] * inv;
        g_expert[t * TOPK + k] = ids[k];
        atomicAdd(&g_cnt[ids[k]], 1);
    }
}

// ---------------- 3. exclusive scan with per-expert padding to BM ----------------
__global__ void k_scan() {
    if (threadIdx.x == 0) {
        int off = 0;
        for (int e = 0; e < NEXP; e++) {
            g_off[e] = off;
            off += ((g_cnt[e] + BM - 1) / BM) * BM;
        }
        g_off[NEXP] = off;
    }
}

// ---------------- 4. scatter: assign slots ----------------
__global__ void k_scatter() {
    int i = blockIdx.x * blockDim.x + threadIdx.x;
    if (i >= TOKENS * TOPK) return;
    int e = g_expert[i];
    int idx = atomicAdd(&g_cursor[e], 1);
    int slot = g_off[e] + idx;
    g_row_src[slot] = i / TOPK;
    g_slot_of[i] = slot;
}

// ---------------- 5. grouped GEMM 1: gate+up fused, SiLU epilogue ----------------
// Block tile 128x64, 8 warps (4x2), each warp 32x32 (2x2 of 16x16), tf32 wmma.
__global__ __launch_bounds__(256) void k_gemm1(
    const float* __restrict__ x,
    const float* __restrict__ Wg,
    const float* __restrict__ Wu)
{
    int e = blockIdx.z;
    int cnt = g_cnt[e];
    if ((int)blockIdx.x * BM >= cnt) return;
    int base = g_off[e];
    int n0 = blockIdx.y * BN;

    __shared__ float sA [BM][BK + 4];
    __shared__ float sBg[BK][BN + 4];
    __shared__ float sBu[BK][BN + 4];

    int tid = threadIdx.x;
    int wid = tid >> 5;
    int wm = wid >> 1;   // 0..3
    int wn = wid & 1;    // 0..1

    wmma::fragment<wmma::accumulator, 16, 16, 8, float> accG[2][2], accU[2][2];
#pragma unroll
    for (int im = 0; im < 2; im++)
#pragma unroll
        for (int in = 0; in < 2; in++) {
            wmma::fill_fragment(accG[im][in], 0.f);
            wmma::fill_fragment(accU[im][in], 0.f);
        }

    const float* Bg = Wg + (size_t)e * HID * INTER + n0;
    const float* Bu = Wu + (size_t)e * HID * INTER + n0;

    // A-gather row mapping: 8 threads per row (32 floats = 8 float4), 32 rows per pass, 4 passes
    int arow = tid >> 3;           // 0..31
    int acol = (tid & 7) * 4;      // 0,4,...,28
    int srcRow[4];
#pragma unroll
    for (int p = 0; p < 4; p++) {
        int r = blockIdx.x * BM + p * 32 + arow;
        srcRow[p] = (r < cnt) ? g_row_src[base + r] : -1;
    }

    int brow = tid >> 4;           // 0..15
    int bcol = (tid & 15) * 4;     // 0..60

    for (int k0 = 0; k0 < HID; k0 += BK) {
#pragma unroll
        for (int p = 0; p < 4; p++) {
            float4 v = make_float4(0.f, 0.f, 0.f, 0.f);
            if (srcRow[p] >= 0)
                v = *(const float4*)(x + (size_t)srcRow[p] * HID + k0 + acol);
            int r = p * 32 + arow;
            sA[r][acol] = v.x; sA[r][acol + 1] = v.y; sA[r][acol + 2] = v.z; sA[r][acol + 3] = v.w;
        }
#pragma unroll
        for (int q = 0; q < 2; q++) {
            int rB = q * 16 + brow;
            float4 vg = *(const float4*)(Bg + (size_t)(k0 + rB) * INTER + bcol);
            float4 vu = *(const float4*)(Bu + (size_t)(k0 + rB) * INTER + bcol);
            sBg[rB][bcol] = vg.x; sBg[rB][bcol + 1] = vg.y; sBg[rB][bcol + 2] = vg.z; sBg[rB][bcol + 3] = vg.w;
            sBu[rB][bcol] = vu.x; sBu[rB][bcol + 1] = vu.y; sBu[rB][bcol + 2] = vu.z; sBu[rB][bcol + 3] = vu.w;
        }
        __syncthreads();

#pragma unroll
        for (int kk = 0; kk < BK; kk += 8) {
            wmma::fragment<wmma::matrix_a, 16, 16, 8, wmma::precision::tf32, wmma::row_major> a[2];
            wmma::fragment<wmma::matrix_b, 16, 16, 8, wmma::precision::tf32, wmma::row_major> bg[2], bu[2];
#pragma unroll
            for (int im = 0; im < 2; im++) {
                wmma::load_matrix_sync(a[im], &sA[wm * 32 + im * 16][kk], BK + 4);
#pragma unroll
                for (int i = 0; i < a[im].num_elements; i++)
                    a[im].x[i] = wmma::__float_to_tf32(a[im].x[i]);
            }
#pragma unroll
            for (int in = 0; in < 2; in++) {
                wmma::load_matrix_sync(bg[in], &sBg[kk][wn * 32 + in * 16], BN + 4);
                wmma::load_matrix_sync(bu[in], &sBu[kk][wn * 32 + in * 16], BN + 4);
#pragma unroll
                for (int i = 0; i < bg[in].num_elements; i++) {
                    bg[in].x[i] = wmma::__float_to_tf32(bg[in].x[i]);
                    bu[in].x[i] = wmma::__float_to_tf32(bu[in].x[i]);
                }
            }
#pragma unroll
            for (int im = 0; im < 2; im++)
#pragma unroll
                for (int in = 0; in < 2; in++) {
                    wmma::mma_sync(accG[im][in], a[im], bg[in], accG[im][in]);
                    wmma::mma_sync(accU[im][in], a[im], bu[in], accU[im][in]);
                }
        }
        __syncthreads();
    }

    // SiLU(gate)*up epilogue, direct store (fragment layouts identical -> elementwise OK)
#pragma unroll
    for (int im = 0; im < 2; im++)
#pragma unroll
        for (int in = 0; in < 2; in++) {
#pragma unroll
            for (int i = 0; i < accG[im][in].num_elements; i++) {
                float g = accG[im][in].x[i];
                float u = accU[im][in].x[i];
                accG[im][in].x[i] = (g / (1.f + expf(-g))) * u;
            }
            size_t row = (size_t)base + blockIdx.x * BM + wm * 32 + im * 16;
            wmma::store_matrix_sync(g_h + row * INTER + n0 + wn * 32 + in * 16,
                                    accG[im][in], INTER, wmma::mem_row_major);
        }
}

// ---------------- 6. grouped GEMM 2: down projection ----------------
__global__ __launch_bounds__(256) void k_gemm2(const float* __restrict__ Wd)
{
    int e = blockIdx.z;
    int cnt = g_cnt[e];
    if ((int)blockIdx.x * BM >= cnt) return;
    int base = g_off[e];
    int n0 = blockIdx.y * BN;

    __shared__ float sA[BM][BK + 4];
    __shared__ float sB[BK][BN + 4];

    int tid = threadIdx.x;
    int wid = tid >> 5;
    int wm = wid >> 1;
    int wn = wid & 1;

    wmma::fragment<wmma::accumulator, 16, 16, 8, float> acc[2][2];
#pragma unroll
    for (int im = 0; im < 2; im++)
#pragma unroll
        for (int in = 0; in < 2; in++)
            wmma::fill_fragment(acc[im][in], 0.f);

    const float* B = Wd + (size_t)e * INTER * HID + n0;
    const float* A = g_h + (size_t)(base + blockIdx.x * BM) * INTER;

    int arow = tid >> 3;
    int acol = (tid & 7) * 4;
    int brow = tid >> 4;
    int bcol = (tid & 15) * 4;

    for (int k0 = 0; k0 < INTER; k0 += BK) {
#pragma unroll
        for (int p = 0; p < 4; p++) {
            int r = p * 32 + arow;
            float4 v = *(const float4*)(A + (size_t)r * INTER + k0 + acol);  // padded rows are zeros
            sA[r][acol] = v.x; sA[r][acol + 1] = v.y; sA[r][acol + 2] = v.z; sA[r][acol + 3] = v.w;
        }
#pragma unroll
        for (int q = 0; q < 2; q++) {
            int rB = q * 16 + brow;
            float4 v = *(const float4*)(B + (size_t)(k0 + rB) * HID + bcol);
            sB[rB][bcol] = v.x; sB[rB][bcol + 1] = v.y; sB[rB][bcol + 2] = v.z; sB[rB][bcol + 3] = v.w;
        }
        __syncthreads();

#pragma unroll
        for (int kk = 0; kk < BK; kk += 8) {
            wmma::fragment<wmma::matrix_a, 16, 16, 8, wmma::precision::tf32, wmma::row_major> a[2];
            wmma::fragment<wmma::matrix_b, 16, 16, 8, wmma::precision::tf32, wmma::row_major> b[2];
#pragma unroll
            for (int im = 0; im < 2; im++) {
                wmma::load_matrix_sync(a[im], &sA[wm * 32 + im * 16][kk], BK + 4);
#pragma unroll
                for (int i = 0; i < a[im].num_elements; i++)
                    a[im].x[i] = wmma::__float_to_tf32(a[im].x[i]);
            }
#pragma unroll
            for (int in = 0; in < 2; in++) {
                wmma::load_matrix_sync(b[in], &sB[kk][wn * 32 + in * 16], BN + 4);
#pragma unroll
                for (int i = 0; i < b[in].num_elements; i++)
                    b[in].x[i] = wmma::__float_to_tf32(b[in].x[i]);
            }
#pragma unroll
            for (int im = 0; im < 2; im++)
#pragma unroll
                for (int in = 0; in < 2; in++)
                    wmma::mma_sync(acc[im][in], a[im], b[in], acc[im][in]);
        }
        __syncthreads();
    }

#pragma unroll
    for (int im = 0; im < 2; im++)
#pragma unroll
        for (int in = 0; in < 2; in++) {
            size_t row = (size_t)base + blockIdx.x * BM + wm * 32 + im * 16;
            wmma::store_matrix_sync(g_down + row * HID + n0 + wn * 32 + in * 16,
                                    acc[im][in], HID, wmma::mem_row_major);
        }
}

// ---------------- 7. combine: weighted sum over top-k ----------------
__global__ void k_combine(float* __restrict__ out) {
    int idx = blockIdx.x * blockDim.x + threadIdx.x;
    const int VPT = HID / 4;  // 512 float4 per token
    if (idx >= TOKENS * VPT) return;
    int t = idx / VPT;
    int c = (idx % VPT) * 4;
    float4 acc = make_float4(0.f, 0.f, 0.f, 0.f);
#pragma unroll
    for (int k = 0; k < TOPK; k++) {
        int slot = g_slot_of[t * TOPK + k];
        float w = g_wt[t * TOPK + k];
        float4 v = *(const float4*)(g_down + (size_t)slot * HID + c);
        acc.x += w * v.x; acc.y += w * v.y; acc.z += w * v.z; acc.w += w * v.w;
    }
    *(float4*)(out + (size_t)t * HID + c) = acc;
}

// ---------------- launch ----------------
extern "C" void kernel_launch(void* const* d_in, const int* in_sizes, int n_in,
                              void* d_out, int out_size)
{
    const float* x      = (const float*)d_in[0];
    const float* logits = (const float*)d_in[1];
    const float* Wg     = (const float*)d_in[2];
    const float* Wu     = (const float*)d_in[3];
    const float* Wd     = (const float*)d_in[4];
    float* out = (float*)d_out;

    k_zero<<<1, 64>>>();
    k_route<<<(TOKENS + 127) / 128, 128>>>(logits);
    k_scan<<<1, 32>>>();
    k_scatter<<<(TOKENS * TOPK + 255) / 256, 256>>>();

    dim3 g1(TOKENS / BM, INTER / BN, NEXP);   // (64, 12, 64)
    k_gemm1<<<g1, 256>>>(x, Wg, Wu);

    dim3 g2(TOKENS / BM, HID / BN, NEXP);     // (64, 32, 64)
    k_gemm2<<<g2, 256>>>(Wd);

    int tot = TOKENS * (HID / 4);
    k_combine<<<(tot + 255) / 256, 256>>>(out);
}

// round 3
// speedup vs baseline: 1.2301x; 1.2301x over previous
#include <cuda_runtime.h>
#include <mma.h>
#include <math.h>
#include <stdint.h>

using namespace nvcuda;

#define TOKENS 8192
#define NEXP   64
#define TOPK   8
#define HID    2048
#define INTER  768

#define BM 128
#define BN 64
#define BK 16

#define MAXROWS (TOKENS * TOPK + NEXP * BM)   // 73728

// ---------------- scratch (static device memory; no allocations) ----------------
__device__ float g_h[(size_t)MAXROWS * INTER];     // silu(gate)*up, per expanded row
__device__ float g_down[(size_t)MAXROWS * HID];    // down-proj result per expanded row
__device__ int   g_row_src[MAXROWS];               // slot -> source token
__device__ int   g_slot_of[TOKENS * TOPK];         // (t,k) -> slot
__device__ float g_wt[TOKENS * TOPK];              // routing weight per (t,k)
__device__ int   g_expert[TOKENS * TOPK];          // expert id per (t,k)
__device__ int   g_cnt[NEXP];
__device__ int   g_cursor[NEXP];
__device__ int   g_off[NEXP + 1];                  // padded group offsets

// ---------------- cp.async helpers ----------------
__device__ __forceinline__ uint32_t smem_u32(const void* p) {
    return (uint32_t)__cvta_generic_to_shared(p);
}
__device__ __forceinline__ void cp16(uint32_t dst, const void* src) {
    asm volatile("cp.async.cg.shared.global [%0], [%1], 16;" :: "r"(dst), "l"(src));
}
__device__ __forceinline__ void cp16z(uint32_t dst, const void* src) {
    // cp-size 16, src-size 0 -> writes 16 bytes of zeros (src not dereferenced)
    asm volatile("cp.async.cg.shared.global [%0], [%1], 16, 0;" :: "r"(dst), "l"(src));
}
__device__ __forceinline__ void cp_commit() { asm volatile("cp.async.commit_group;"); }
__device__ __forceinline__ void cp_wait0()  { asm volatile("cp.async.wait_group 0;"); }

// ---------------- 1. zero counters ----------------
__global__ void k_zero() {
    int i = threadIdx.x;
    if (i < NEXP) { g_cnt[i] = 0; g_cursor[i] = 0; }
}

// ---------------- 2. routing: top-8 + softmax + histogram ----------------
__global__ void k_route(const float* __restrict__ logits) {
    int t = blockIdx.x * blockDim.x + threadIdx.x;
    if (t >= TOKENS) return;
    float l[NEXP];
#pragma unroll
    for (int i = 0; i < NEXP; i++) l[i] = logits[t * NEXP + i];

    float vals[TOPK]; int ids[TOPK];
#pragma unroll
    for (int k = 0; k < TOPK; k++) {
        float best = -INFINITY; int bi = 0;
#pragma unroll
        for (int i = 0; i < NEXP; i++) {
            if (l[i] > best) { best = l[i]; bi = i; }
        }
        vals[k] = best; ids[k] = bi;
        l[bi] = -INFINITY;
    }
    float m = vals[0];
    float ex[TOPK]; float s = 0.f;
#pragma unroll
    for (int k = 0; k < TOPK; k++) { ex[k] = expf(vals[k] - m); s += ex[k]; }
    float inv = 1.f / s;
#pragma unroll
    for (int k = 0; k < TOPK; k++) {
        g_wt[t * TOPK + k] = ex[k] * inv;
        g_expert[t * TOPK + k] = ids[k];
        atomicAdd(&g_cnt[ids[k]], 1);
    }
}

// ---------------- 3. exclusive scan with per-expert padding to BM ----------------
__global__ void k_scan() {
    if (threadIdx.x == 0) {
        int off = 0;
        for (int e = 0; e < NEXP; e++) {
            g_off[e] = off;
            off += ((g_cnt[e] + BM - 1) / BM) * BM;
        }
        g_off[NEXP] = off;
    }
}

// ---------------- 4. scatter: assign slots ----------------
__global__ void k_scatter() {
    int i = blockIdx.x * blockDim.x + threadIdx.x;
    if (i >= TOKENS * TOPK) return;
    int e = g_expert[i];
    int idx = atomicAdd(&g_cursor[e], 1);
    int slot = g_off[e] + idx;
    g_row_src[slot] = i / TOPK;
    g_slot_of[i] = slot;
}

// ---------------- 5. grouped GEMM 1: gate+up fused, SiLU epilogue ----------------
// Block tile 128x64 (x2 B-matrices), 8 warps (4x2), warp 32x32, tf32 wmma.
// 2-stage cp.async double-buffered pipeline, BK=16.
__global__ __launch_bounds__(256) void k_gemm1(
    const float* __restrict__ x,
    const float* __restrict__ Wg,
    const float* __restrict__ Wu)
{
    int e = blockIdx.z;
    int cnt = g_cnt[e];
    if ((int)blockIdx.x * BM >= cnt) return;
    int base = g_off[e];
    int n0 = blockIdx.y * BN;

    __shared__ float sA [2][BM][BK + 4];
    __shared__ float sBg[2][BK][BN + 4];
    __shared__ float sBu[2][BK][BN + 4];

    int tid = threadIdx.x;
    int wid = tid >> 5;
    int wm = wid >> 1;   // 0..3
    int wn = wid & 1;    // 0..1

    // A: 4 threads/row (16 floats = 4 float4), 64 rows/pass, 2 passes
    int arow = tid >> 2;           // 0..63
    int acol = (tid & 3) << 2;     // 0,4,8,12
    const float* aptr[2];
#pragma unroll
    for (int p = 0; p < 2; p++) {
        int r = blockIdx.x * BM + p * 64 + arow;
        int s = (r < cnt) ? g_row_src[base + r] : -1;
        aptr[p] = (s >= 0) ? (x + (size_t)s * HID + acol) : nullptr;
    }
    // B: 16x64 floats = 256 float4 -> 1 per thread per matrix
    int brow = tid >> 4;           // 0..15
    int bcol = (tid & 15) << 2;    // 0..60
    const float* bg = Wg + (size_t)e * HID * INTER + (size_t)brow * INTER + n0 + bcol;
    const float* bu = Wu + (size_t)e * HID * INTER + (size_t)brow * INTER + n0 + bcol;

    wmma::fragment<wmma::accumulator, 16, 16, 8, float> accG[2][2], accU[2][2];
#pragma unroll
    for (int im = 0; im < 2; im++)
#pragma unroll
        for (int in = 0; in < 2; in++) {
            wmma::fill_fragment(accG[im][in], 0.f);
            wmma::fill_fragment(accU[im][in], 0.f);
        }

    auto load_tile = [&](int buf, int k0) {
#pragma unroll
        for (int p = 0; p < 2; p++) {
            uint32_t d = smem_u32(&sA[buf][p * 64 + arow][acol]);
            if (aptr[p]) cp16(d, aptr[p] + k0);
            else         cp16z(d, x);
        }
        cp16(smem_u32(&sBg[buf][brow][bcol]), bg + (size_t)k0 * INTER);
        cp16(smem_u32(&sBu[buf][brow][bcol]), bu + (size_t)k0 * INTER);
    };

    load_tile(0, 0);
    cp_commit();

    int buf = 0;
    for (int k0 = 0; k0 < HID; k0 += BK) {
        cp_wait0();
        __syncthreads();
        if (k0 + BK < HID) { load_tile(buf ^ 1, k0 + BK); cp_commit(); }

#pragma unroll
        for (int kk = 0; kk < BK; kk += 8) {
            wmma::fragment<wmma::matrix_a, 16, 16, 8, wmma::precision::tf32, wmma::row_major> a[2];
            wmma::fragment<wmma::matrix_b, 16, 16, 8, wmma::precision::tf32, wmma::row_major> fg[2], fu[2];
#pragma unroll
            for (int im = 0; im < 2; im++) {
                wmma::load_matrix_sync(a[im], &sA[buf][wm * 32 + im * 16][kk], BK + 4);
#pragma unroll
                for (int i = 0; i < a[im].num_elements; i++)
                    a[im].x[i] = wmma::__float_to_tf32(a[im].x[i]);
            }
#pragma unroll
            for (int in = 0; in < 2; in++) {
                wmma::load_matrix_sync(fg[in], &sBg[buf][kk][wn * 32 + in * 16], BN + 4);
                wmma::load_matrix_sync(fu[in], &sBu[buf][kk][wn * 32 + in * 16], BN + 4);
#pragma unroll
                for (int i = 0; i < fg[in].num_elements; i++) {
                    fg[in].x[i] = wmma::__float_to_tf32(fg[in].x[i]);
                    fu[in].x[i] = wmma::__float_to_tf32(fu[in].x[i]);
                }
            }
#pragma unroll
            for (int im = 0; im < 2; im++)
#pragma unroll
                for (int in = 0; in < 2; in++) {
                    wmma::mma_sync(accG[im][in], a[im], fg[in], accG[im][in]);
                    wmma::mma_sync(accU[im][in], a[im], fu[in], accU[im][in]);
                }
        }
        buf ^= 1;
    }

    // SiLU(gate)*up epilogue
#pragma unroll
    for (int im = 0; im < 2; im++)
#pragma unroll
        for (int in = 0; in < 2; in++) {
#pragma unroll
            for (int i = 0; i < accG[im][in].num_elements; i++) {
                float g = accG[im][in].x[i];
                float u = accU[im][in].x[i];
                accG[im][in].x[i] = (g / (1.f + expf(-g))) * u;
            }
            size_t row = (size_t)base + blockIdx.x * BM + wm * 32 + im * 16;
            wmma::store_matrix_sync(g_h + row * INTER + n0 + wn * 32 + in * 16,
                                    accG[im][in], INTER, wmma::mem_row_major);
        }
}

// ---------------- 6. grouped GEMM 2: down projection ----------------
__global__ __launch_bounds__(256) void k_gemm2(const float* __restrict__ Wd)
{
    int e = blockIdx.z;
    int cnt = g_cnt[e];
    if ((int)blockIdx.x * BM >= cnt) return;
    int base = g_off[e];
    int n0 = blockIdx.y * BN;

    __shared__ float sA[2][BM][BK + 4];
    __shared__ float sB[2][BK][BN + 4];

    int tid = threadIdx.x;
    int wid = tid >> 5;
    int wm = wid >> 1;
    int wn = wid & 1;

    int arow = tid >> 2;
    int acol = (tid & 3) << 2;
    const float* A = g_h + (size_t)(base + blockIdx.x * BM) * INTER;

    int brow = tid >> 4;
    int bcol = (tid & 15) << 2;
    const float* B = Wd + (size_t)e * INTER * HID + (size_t)brow * HID + n0 + bcol;

    wmma::fragment<wmma::accumulator, 16, 16, 8, float> acc[2][2];
#pragma unroll
    for (int im = 0; im < 2; im++)
#pragma unroll
        for (int in = 0; in < 2; in++)
            wmma::fill_fragment(acc[im][in], 0.f);

    auto load_tile = [&](int buf, int k0) {
#pragma unroll
        for (int p = 0; p < 2; p++) {
            int r = p * 64 + arow;
            cp16(smem_u32(&sA[buf][r][acol]), A + (size_t)r * INTER + k0 + acol);
        }
        cp16(smem_u32(&sB[buf][brow][bcol]), B + (size_t)k0 * HID);
    };

    load_tile(0, 0);
    cp_commit();

    int buf = 0;
    for (int k0 = 0; k0 < INTER; k0 += BK) {
        cp_wait0();
        __syncthreads();
        if (k0 + BK < INTER) { load_tile(buf ^ 1, k0 + BK); cp_commit(); }

#pragma unroll
        for (int kk = 0; kk < BK; kk += 8) {
            wmma::fragment<wmma::matrix_a, 16, 16, 8, wmma::precision::tf32, wmma::row_major> a[2];
            wmma::fragment<wmma::matrix_b, 16, 16, 8, wmma::precision::tf32, wmma::row_major> b[2];
#pragma unroll
            for (int im = 0; im < 2; im++) {
                wmma::load_matrix_sync(a[im], &sA[buf][wm * 32 + im * 16][kk], BK + 4);
#pragma unroll
                for (int i = 0; i < a[im].num_elements; i++)
                    a[im].x[i] = wmma::__float_to_tf32(a[im].x[i]);
            }
#pragma unroll
            for (int in = 0; in < 2; in++) {
                wmma::load_matrix_sync(b[in], &sB[buf][kk][wn * 32 + in * 16], BN + 4);
#pragma unroll
                for (int i = 0; i < b[in].num_elements; i++)
                    b[in].x[i] = wmma::__float_to_tf32(b[in].x[i]);
            }
#pragma unroll
            for (int im = 0; im < 2; im++)
#pragma unroll
                for (int in = 0; in < 2; in++)
                    wmma::mma_sync(acc[im][in], a[im], b[in], acc[im][in]);
        }
        buf ^= 1;
    }

#pragma unroll
    for (int im = 0; im < 2; im++)
#pragma unroll
        for (int in = 0; in < 2; in++) {
            size_t row = (size_t)base + blockIdx.x * BM + wm * 32 + im * 16;
            wmma::store_matrix_sync(g_down + row * HID + n0 + wn * 32 + in * 16,
                                    acc[im][in], HID, wmma::mem_row_major);
        }
}

// ---------------- 7. combine: weighted sum over top-k ----------------
__global__ void k_combine(float* __restrict__ out) {
    int idx = blockIdx.x * blockDim.x + threadIdx.x;
    const int VPT = HID / 4;
    if (idx >= TOKENS * VPT) return;
    int t = idx / VPT;
    int c = (idx % VPT) * 4;
    float4 acc = make_float4(0.f, 0.f, 0.f, 0.f);
#pragma unroll
    for (int k = 0; k < TOPK; k++) {
        int slot = g_slot_of[t * TOPK + k];
        float w = g_wt[t * TOPK + k];
        float4 v = *(const float4*)(g_down + (size_t)slot * HID + c);
        acc.x += w * v.x; acc.y += w * v.y; acc.z += w * v.z; acc.w += w * v.w;
    }
    *(float4*)(out + (size_t)t * HID + c) = acc;
}

// ---------------- launch ----------------
extern "C" void kernel_launch(void* const* d_in, const int* in_sizes, int n_in,
                              void* d_out, int out_size)
{
    const float* x      = (const float*)d_in[0];
    const float* logits = (const float*)d_in[1];
    const float* Wg     = (const float*)d_in[2];
    const float* Wu     = (const float*)d_in[3];
    const float* Wd     = (const float*)d_in[4];
    float* out = (float*)d_out;

    k_zero<<<1, 64>>>();
    k_route<<<(TOKENS + 127) / 128, 128>>>(logits);
    k_scan<<<1, 32>>>();
    k_scatter<<<(TOKENS * TOPK + 255) / 256, 256>>>();

    dim3 g1(TOKENS / BM, INTER / BN, NEXP);   // (64, 12, 64)
    k_gemm1<<<g1, 256>>>(x, Wg, Wu);

    dim3 g2(TOKENS / BM, HID / BN, NEXP);     // (64, 32, 64)
    k_gemm2<<<g2, 256>>>(Wd);

    int tot = TOKENS * (HID / 4);
    k_combine<<<(tot + 255) / 256, 256>>>(out);
}

// round 6
// speedup vs baseline: 2.8932x; 2.3520x over previous
#include <cuda_runtime.h>
#include <mma.h>
#include <math.h>
#include <stdint.h>

using namespace nvcuda;

// tcgen05 is only legal in arch-accelerated ('a') compile passes.
#if defined(__CUDA_ARCH_FEAT_SM103_ALL) || defined(__CUDA_ARCH_FEAT_SM100_ALL) || defined(__CUDA_ARCH_FEAT_SM101_ALL)
#define TC_OK 1
#else
#define TC_OK 0
#endif

#define TOKENS 8192
#define NEXP   64
#define TOPK   8
#define HID    2048
#define INTER  768
#define BM     128
#define MT_MAX 24

#define MAXROWS (TOKENS * TOPK + NEXP * BM)

// ---------------- scratch (static device memory) ----------------
__device__ float g_xr[(size_t)TOKENS * HID];       // tf32-rounded X (tcgen05 path)
__device__ float g_h[(size_t)MAXROWS * INTER];     // silu(gate)*up
__device__ float g_down[(size_t)MAXROWS * HID];
__device__ int   g_row_src[MAXROWS];
__device__ int   g_slot_of[TOKENS * TOPK];
__device__ float g_wt[TOKENS * TOPK];
__device__ int   g_expert[TOKENS * TOPK];
__device__ int   g_cnt[NEXP];
__device__ int   g_cursor[NEXP];
__device__ int   g_off[NEXP + 1];

// ---------------- common PTX helpers ----------------
__device__ __forceinline__ uint32_t smem_u32(const void* p) {
    return (uint32_t)__cvta_generic_to_shared(p);
}
__device__ __forceinline__ void cp16(uint32_t dst, const void* src) {
    asm volatile("cp.async.cg.shared.global [%0], [%1], 16;" :: "r"(dst), "l"(src));
}
__device__ __forceinline__ void cp16z(uint32_t dst, const void* src) {
    asm volatile("cp.async.cg.shared.global [%0], [%1], 16, 0;" :: "r"(dst), "l"(src));
}
__device__ __forceinline__ void cp_commit() { asm volatile("cp.async.commit_group;"); }
__device__ __forceinline__ void cp_wait0()  { asm volatile("cp.async.wait_group 0;"); }

__device__ __forceinline__ float tf32r(float x) {
    float r; asm("cvt.rna.tf32.f32 %0, %1;" : "=f"(r) : "f"(x)); return r;
}
__device__ __forceinline__ void sts64f(uint32_t addr, float a, float b) {
    asm volatile("{ .reg .b64 t; mov.b64 t, {%1, %2}; st.shared.b64 [%0], t; }"
                 :: "r"(addr), "f"(a), "f"(b) : "memory");
}

// ---------------- small kernels (shared by both paths) ----------------
__global__ void k_zero() {
    int i = threadIdx.x;
    if (i < NEXP) { g_cnt[i] = 0; g_cursor[i] = 0; }
}

__global__ void k_route(const float* __restrict__ logits) {
    int t = blockIdx.x * blockDim.x + threadIdx.x;
    if (t >= TOKENS) return;
    float l[NEXP];
#pragma unroll
    for (int i = 0; i < NEXP; i++) l[i] = logits[t * NEXP + i];
    float vals[TOPK]; int ids[TOPK];
#pragma unroll
    for (int k = 0; k < TOPK; k++) {
        float best = -INFINITY; int bi = 0;
#pragma unroll
        for (int i = 0; i < NEXP; i++)
            if (l[i] > best) { best = l[i]; bi = i; }
        vals[k] = best; ids[k] = bi; l[bi] = -INFINITY;
    }
    float m = vals[0], s = 0.f, ex[TOPK];
#pragma unroll
    for (int k = 0; k < TOPK; k++) { ex[k] = expf(vals[k] - m); s += ex[k]; }
    float inv = 1.f / s;
#pragma unroll
    for (int k = 0; k < TOPK; k++) {
        g_wt[t * TOPK + k] = ex[k] * inv;
        g_expert[t * TOPK + k] = ids[k];
        atomicAdd(&g_cnt[ids[k]], 1);
    }
}

__global__ void k_scan() {
    if (threadIdx.x == 0) {
        int off = 0;
        for (int e = 0; e < NEXP; e++) {
            g_off[e] = off;
            off += ((g_cnt[e] + BM - 1) / BM) * BM;
        }
        g_off[NEXP] = off;
    }
}

__global__ void k_scatter() {
    int i = blockIdx.x * blockDim.x + threadIdx.x;
    if (i >= TOKENS * TOPK) return;
    int e = g_expert[i];
    int idx = atomicAdd(&g_cursor[e], 1);
    int slot = g_off[e] + idx;
    g_row_src[slot] = i / TOPK;
    g_slot_of[i] = slot;
}

__global__ void k_xround(const float* __restrict__ x) {
    size_t i = (size_t)blockIdx.x * blockDim.x + threadIdx.x;
    if (i >= (size_t)TOKENS * HID / 4) return;
    float4 v = ((const float4*)x)[i];
    v.x = tf32r(v.x); v.y = tf32r(v.y); v.z = tf32r(v.z); v.w = tf32r(v.w);
    ((float4*)g_xr)[i] = v;
}

__global__ void k_combine(float* __restrict__ out) {
    int idx = blockIdx.x * blockDim.x + threadIdx.x;
    const int VPT = HID / 4;
    if (idx >= TOKENS * VPT) return;
    int t = idx / VPT;
    int c = (idx % VPT) * 4;
    float4 acc = make_float4(0.f, 0.f, 0.f, 0.f);
#pragma unroll
    for (int k = 0; k < TOPK; k++) {
        int slot = g_slot_of[t * TOPK + k];
        float w = g_wt[t * TOPK + k];
        float4 v = *(const float4*)(g_down + (size_t)slot * HID + c);
        acc.x += w * v.x; acc.y += w * v.y; acc.z += w * v.z; acc.w += w * v.w;
    }
    *(float4*)(out + (size_t)t * HID + c) = acc;
}

// ============================================================================
// tcgen05 path (bodies only in 'a' passes)
// ============================================================================
#if TC_OK
__device__ __forceinline__ uint32_t elect_one() {
    uint32_t p;
    asm volatile("{\n\t.reg .pred p;\n\telect.sync _|p, 0xFFFFFFFF;\n\tselp.b32 %0, 1, 0, p;\n\t}" : "=r"(p));
    return p;
}

#define MBAR_INIT(addr, cnt) \
    asm volatile("mbarrier.init.shared.b64 [%0], %1;" :: "r"(addr), "r"(cnt) : "memory")
#define MBAR_WAIT(addr, parity) do { \
    uint32_t _m = (addr), _p = (parity); \
    asm volatile("{\n\t.reg .pred P;\n\tWL_%=:\n\t" \
        "mbarrier.try_wait.parity.acquire.cta.shared::cta.b64 P, [%0], %1, 0x989680;\n\t" \
        "@P bra.uni WD_%=;\n\tbra.uni WL_%=;\n\tWD_%=:\n\t}" \
        :: "r"(_m), "r"(_p) : "memory"); } while (0)

#define TC_ALLOC(dst, n)  asm volatile("tcgen05.alloc.cta_group::1.sync.aligned.shared::cta.b32 [%0], %1;" :: "r"(dst), "r"(n) : "memory")
#define TC_DEALLOC(t, n)  asm volatile("tcgen05.dealloc.cta_group::1.sync.aligned.b32 %0, %1;" :: "r"(t), "r"(n))
#define TC_RELINQ()       asm volatile("tcgen05.relinquish_alloc_permit.cta_group::1.sync.aligned;")
#define TC_COMMIT(mb)     asm volatile("tcgen05.commit.cta_group::1.mbarrier::arrive::one.shared::cluster.b64 [%0];" :: "r"(mb) : "memory")
#define TC_FENCE_AFTER()  asm volatile("tcgen05.fence::after_thread_sync;" ::: "memory")
#define TC_FENCE_BEFORE() asm volatile("tcgen05.fence::before_thread_sync;" ::: "memory")
#define TC_WAIT_LD()      asm volatile("tcgen05.wait::ld.sync.aligned;" ::: "memory")
#define FENCE_ASYNC()     asm volatile("fence.proxy.async.shared::cta;" ::: "memory")

#define TC_LD_X16(r, addr) \
    asm volatile("tcgen05.ld.sync.aligned.32x32b.x16.b32 " \
        "{%0,%1,%2,%3,%4,%5,%6,%7,%8,%9,%10,%11,%12,%13,%14,%15}, [%16];" \
        : "=r"((r)[0]), "=r"((r)[1]), "=r"((r)[2]), "=r"((r)[3]), \
          "=r"((r)[4]), "=r"((r)[5]), "=r"((r)[6]), "=r"((r)[7]), \
          "=r"((r)[8]), "=r"((r)[9]), "=r"((r)[10]), "=r"((r)[11]), \
          "=r"((r)[12]), "=r"((r)[13]), "=r"((r)[14]), "=r"((r)[15]) \
        : "r"(addr))

#define TC_LD_X32(r, addr) \
    asm volatile("tcgen05.ld.sync.aligned.32x32b.x32.b32 " \
        "{%0,%1,%2,%3,%4,%5,%6,%7,%8,%9,%10,%11,%12,%13,%14,%15," \
        "%16,%17,%18,%19,%20,%21,%22,%23,%24,%25,%26,%27,%28,%29,%30,%31}, [%32];" \
        : "=r"((r)[0]), "=r"((r)[1]), "=r"((r)[2]), "=r"((r)[3]), \
          "=r"((r)[4]), "=r"((r)[5]), "=r"((r)[6]), "=r"((r)[7]), \
          "=r"((r)[8]), "=r"((r)[9]), "=r"((r)[10]), "=r"((r)[11]), \
          "=r"((r)[12]), "=r"((r)[13]), "=r"((r)[14]), "=r"((r)[15]), \
          "=r"((r)[16]), "=r"((r)[17]), "=r"((r)[18]), "=r"((r)[19]), \
          "=r"((r)[20]), "=r"((r)[21]), "=r"((r)[22]), "=r"((r)[23]), \
          "=r"((r)[24]), "=r"((r)[25]), "=r"((r)[26]), "=r"((r)[27]), \
          "=r"((r)[28]), "=r"((r)[29]), "=r"((r)[30]), "=r"((r)[31]) \
        : "r"(addr))

__device__ __forceinline__ void mma_tf32(uint32_t d_tmem, uint64_t a_desc, uint64_t b_desc,
                                         uint32_t idesc, bool acc) {
    uint32_t en = acc ? 1u : 0u;
    asm volatile("{\n\t.reg .pred p;\n\tsetp.ne.u32 p, %5, 0;\n\t"
                 "tcgen05.mma.cta_group::1.kind::tf32 [%0], %1, %2, %3, {%4, %4, %4, %4}, p;\n\t}"
                 :: "r"(d_tmem), "l"(a_desc), "l"(b_desc), "r"(idesc), "r"(0u), "r"(en)
                 : "memory");
}

__device__ __forceinline__ uint64_t mkdesc(uint32_t addr) {
    const uint64_t base = (2ull << 61) | (1ull << 46) | (64ull << 32) | (1ull << 16);
    return base | ((uint64_t)(addr >> 4) & 0x3FFF);
}

#define IDESC_N128 ((1u << 4) | (2u << 7) | (2u << 10) | (16u << 17) | (8u << 24))
#define IDESC_N256 ((1u << 4) | (2u << 7) | (2u << 10) | (32u << 17) | (8u << 24))
#endif  // TC_OK

// ---------------- GEMM1 tcgen05: gate+up, BM=128, BN=128 (x2 mats), BK=32 ----------------
__global__ void __launch_bounds__(256, 2) k_gemm1_tc(const float* __restrict__ Wg,
                                                     const float* __restrict__ Wu)
{
#if TC_OK
    int e = blockIdx.z;
    int cnt = g_cnt[e];
    int mtile = blockIdx.x;
    if (mtile * BM >= cnt) return;
    int base = g_off[e];
    int n0 = blockIdx.y * 128;

    extern __shared__ char dsm[];
    __shared__ uint32_t s_tmem;
    __shared__ uint64_t s_mbar[2];
    uint32_t sbase = (smem_u32(dsm) + 1023) & ~1023u;
    uint32_t sA[2]  = { sbase,          sbase + 16384 };
    uint32_t sBg[2] = { sbase + 32768,  sbase + 49152 };
    uint32_t sBu[2] = { sbase + 65536,  sbase + 81920 };

    int tid = threadIdx.x, wid = tid >> 5, lane = tid & 31;

    if (tid == 0) {
        MBAR_INIT(smem_u32(&s_mbar[0]), 1);
        MBAR_INIT(smem_u32(&s_mbar[1]), 1);
    }
    if (wid == 0) { TC_ALLOC(smem_u32(&s_tmem), 256); TC_RELINQ(); }
    __syncthreads();
    uint32_t tmem = s_tmem;

    int c8 = tid & 7;
    const float* asrc[4];
    uint32_t adst[4];
#pragma unroll
    for (int p = 0; p < 4; p++) {
        int r = (tid >> 3) + p * 32;
        int gr = mtile * BM + r;
        int s = (gr < cnt) ? g_row_src[base + gr] : -1;
        asrc[p] = (s >= 0) ? (g_xr + (size_t)s * HID + c8 * 4) : nullptr;
        adst[p] = (uint32_t)(r * 128 + ((c8 ^ (r & 7)) * 16));
    }

    const float* wgb = Wg + (size_t)e * HID * INTER + n0;
    const float* wub = Wu + (size_t)e * HID * INTER + n0;

    int ph[2] = { 0, 0 };
    const int KT = HID / 32;   // 64

    for (int it = 0; it < KT; it++) {
        int b = it & 1;
        if (it >= 2) { MBAR_WAIT(smem_u32(&s_mbar[b]), ph[b]); ph[b] ^= 1; }
        int k0 = it * 32;

#pragma unroll
        for (int p = 0; p < 4; p++) {
            if (asrc[p]) cp16(sA[b] + adst[p], asrc[p] + k0);
            else         cp16z(sA[b] + adst[p], g_xr);
        }
        cp_commit();

#pragma unroll
        for (int q = 0; q < 2; q++) {
            int slot = tid + q * 256;
            int kp = slot >> 5;
            int n  = (slot & 31) * 4;
            int k  = kp * 2;
            const float* pg = wgb + (size_t)(k0 + k) * INTER + n;
            const float* pu = wub + (size_t)(k0 + k) * INTER + n;
            float4 g0 = *(const float4*)pg;
            float4 g1 = *(const float4*)(pg + INTER);
            float4 u0 = *(const float4*)pu;
            float4 u1 = *(const float4*)(pu + INTER);
            const float* g0a = (const float*)&g0; const float* g1a = (const float*)&g1;
            const float* u0a = (const float*)&u0; const float* u1a = (const float*)&u1;
#pragma unroll
            for (int j = 0; j < 4; j++) {
                uint32_t addr = (uint32_t)((n + j) * 128 + ((k * 4) ^ (((n + j) & 7) * 16)));
                sts64f(sBg[b] + addr, tf32r(g0a[j]), tf32r(g1a[j]));
                sts64f(sBu[b] + addr, tf32r(u0a[j]), tf32r(u1a[j]));
            }
        }
        cp_wait0();
        __syncthreads();

        if (wid == 0) {
            FENCE_ASYNC();
            if (elect_one()) {
                uint64_t da = mkdesc(sA[b]);
                uint64_t dg = mkdesc(sBg[b]);
                uint64_t du = mkdesc(sBu[b]);
#pragma unroll
                for (int ks = 0; ks < 4; ks++) {
                    bool acc = !(it == 0 && ks == 0);
                    mma_tf32(tmem,       da + 2 * ks, dg + 2 * ks, IDESC_N128, acc);
                    mma_tf32(tmem + 128, da + 2 * ks, du + 2 * ks, IDESC_N128, acc);
                }
                TC_COMMIT(smem_u32(&s_mbar[b]));
            }
        }
    }

    int bl = (KT - 1) & 1;
    MBAR_WAIT(smem_u32(&s_mbar[bl]), ph[bl]);
    TC_FENCE_AFTER();

    if (wid < 4) {
        int m = wid * 32 + lane;
        float* dst = g_h + (size_t)(base + mtile * BM + m) * INTER + n0;
#pragma unroll
        for (int c0 = 0; c0 < 128; c0 += 16) {
            uint32_t rg[16], ru[16];
            TC_LD_X16(rg, tmem + c0);
            TC_LD_X16(ru, tmem + 128 + c0);
            TC_WAIT_LD();
#pragma unroll
            for (int j = 0; j < 16; j++) {
                float g = __uint_as_float(rg[j]);
                float u = __uint_as_float(ru[j]);
                float h = (g / (1.f + __expf(-g))) * u;
                rg[j] = __float_as_uint(tf32r(h));
            }
#pragma unroll
            for (int j = 0; j < 16; j += 4)
                *(uint4*)(dst + c0 + j) = make_uint4(rg[j], rg[j+1], rg[j+2], rg[j+3]);
        }
        TC_FENCE_BEFORE();
    }
    __syncthreads();
    if (wid == 0) TC_DEALLOC(tmem, 256);
#endif
}

// ---------------- GEMM2 tcgen05: down proj, BM=128, BN=256, BK=32 ----------------
__global__ void __launch_bounds__(256, 2) k_gemm2_tc(const float* __restrict__ Wd)
{
#if TC_OK
    int e = blockIdx.z;
    int cnt = g_cnt[e];
    int mtile = blockIdx.x;
    if (mtile * BM >= cnt) return;
    int base = g_off[e];
    int n0 = blockIdx.y * 256;

    extern __shared__ char dsm[];
    __shared__ uint32_t s_tmem;
    __shared__ uint64_t s_mbar[2];
    uint32_t sbase = (smem_u32(dsm) + 1023) & ~1023u;
    uint32_t sA[2] = { sbase,         sbase + 16384 };
    uint32_t sB[2] = { sbase + 32768, sbase + 65536 };

    int tid = threadIdx.x, wid = tid >> 5, lane = tid & 31;

    if (tid == 0) {
        MBAR_INIT(smem_u32(&s_mbar[0]), 1);
        MBAR_INIT(smem_u32(&s_mbar[1]), 1);
    }
    if (wid == 0) { TC_ALLOC(smem_u32(&s_tmem), 256); TC_RELINQ(); }
    __syncthreads();
    uint32_t tmem = s_tmem;

    int c8 = tid & 7;
    const float* asrc[4];
    uint32_t adst[4];
#pragma unroll
    for (int p = 0; p < 4; p++) {
        int r = (tid >> 3) + p * 32;
        asrc[p] = g_h + (size_t)(base + mtile * BM + r) * INTER + c8 * 4;
        adst[p] = (uint32_t)(r * 128 + ((c8 ^ (r & 7)) * 16));
    }

    const float* wdb = Wd + (size_t)e * INTER * HID + n0;

    int ph[2] = { 0, 0 };
    const int KT = INTER / 32;   // 24

    for (int it = 0; it < KT; it++) {
        int b = it & 1;
        if (it >= 2) { MBAR_WAIT(smem_u32(&s_mbar[b]), ph[b]); ph[b] ^= 1; }
        int k0 = it * 32;

#pragma unroll
        for (int p = 0; p < 4; p++)
            cp16(sA[b] + adst[p], asrc[p] + k0);
        cp_commit();

#pragma unroll
        for (int q = 0; q < 4; q++) {
            int slot = tid + q * 256;
            int kp = slot >> 6;
            int n  = (slot & 63) * 4;
            int k  = kp * 2;
            const float* pw = wdb + (size_t)(k0 + k) * HID + n;
            float4 w0 = *(const float4*)pw;
            float4 w1 = *(const float4*)(pw + HID);
            const float* w0a = (const float*)&w0; const float* w1a = (const float*)&w1;
#pragma unroll
            for (int j = 0; j < 4; j++) {
                uint32_t addr = (uint32_t)((n + j) * 128 + ((k * 4) ^ (((n + j) & 7) * 16)));
                sts64f(sB[b] + addr, tf32r(w0a[j]), tf32r(w1a[j]));
            }
        }
        cp_wait0();
        __syncthreads();

        if (wid == 0) {
            FENCE_ASYNC();
            if (elect_one()) {
                uint64_t da = mkdesc(sA[b]);
                uint64_t db = mkdesc(sB[b]);
#pragma unroll
                for (int ks = 0; ks < 4; ks++) {
                    bool acc = !(it == 0 && ks == 0);
                    mma_tf32(tmem, da + 2 * ks, db + 2 * ks, IDESC_N256, acc);
                }
                TC_COMMIT(smem_u32(&s_mbar[b]));
            }
        }
    }

    int bl = (KT - 1) & 1;
    MBAR_WAIT(smem_u32(&s_mbar[bl]), ph[bl]);
    TC_FENCE_AFTER();

    if (wid < 4) {
        int m = wid * 32 + lane;
        float* dst = g_down + (size_t)(base + mtile * BM + m) * HID + n0;
#pragma unroll
        for (int c0 = 0; c0 < 256; c0 += 32) {
            uint32_t r[32];
            TC_LD_X32(r, tmem + c0);
            TC_WAIT_LD();
#pragma unroll
            for (int j = 0; j < 32; j += 4)
                *(uint4*)(dst + c0 + j) = make_uint4(r[j], r[j+1], r[j+2], r[j+3]);
        }
        TC_FENCE_BEFORE();
    }
    __syncthreads();
    if (wid == 0) TC_DEALLOC(tmem, 256);
#endif
}

// ============================================================================
// wmma fallback path (bodies only in non-'a' device passes; host pass also
// compiles them, which is harmless)
// ============================================================================
#define FBK 16

__global__ void __launch_bounds__(256) k_gemm1_wm(
    const float* __restrict__ x,
    const float* __restrict__ Wg,
    const float* __restrict__ Wu)
{
#if !TC_OK
    int e = blockIdx.z;
    int cnt = g_cnt[e];
    if ((int)blockIdx.x * BM >= cnt) return;
    int base = g_off[e];
    int n0 = blockIdx.y * 64;

    __shared__ float sA [2][BM][FBK + 4];
    __shared__ float sBg[2][FBK][64 + 4];
    __shared__ float sBu[2][FBK][64 + 4];

    int tid = threadIdx.x;
    int wid = tid >> 5;
    int wm = wid >> 1;
    int wn = wid & 1;

    int arow = tid >> 2;
    int acol = (tid & 3) << 2;
    const float* aptr[2];
#pragma unroll
    for (int p = 0; p < 2; p++) {
        int r = blockIdx.x * BM + p * 64 + arow;
        int s = (r < cnt) ? g_row_src[base + r] : -1;
        aptr[p] = (s >= 0) ? (x + (size_t)s * HID + acol) : nullptr;
    }
    int brow = tid >> 4;
    int bcol = (tid & 15) << 2;
    const float* bg = Wg + (size_t)e * HID * INTER + (size_t)brow * INTER + n0 + bcol;
    const float* bu = Wu + (size_t)e * HID * INTER + (size_t)brow * INTER + n0 + bcol;

    wmma::fragment<wmma::accumulator, 16, 16, 8, float> accG[2][2], accU[2][2];
#pragma unroll
    for (int im = 0; im < 2; im++)
#pragma unroll
        for (int in = 0; in < 2; in++) {
            wmma::fill_fragment(accG[im][in], 0.f);
            wmma::fill_fragment(accU[im][in], 0.f);
        }

    auto load_tile = [&](int buf, int k0) {
#pragma unroll
        for (int p = 0; p < 2; p++) {
            uint32_t d = smem_u32(&sA[buf][p * 64 + arow][acol]);
            if (aptr[p]) cp16(d, aptr[p] + k0);
            else         cp16z(d, x);
        }
        cp16(smem_u32(&sBg[buf][brow][bcol]), bg + (size_t)k0 * INTER);
        cp16(smem_u32(&sBu[buf][brow][bcol]), bu + (size_t)k0 * INTER);
    };

    load_tile(0, 0);
    cp_commit();

    int buf = 0;
    for (int k0 = 0; k0 < HID; k0 += FBK) {
        cp_wait0();
        __syncthreads();
        if (k0 + FBK < HID) { load_tile(buf ^ 1, k0 + FBK); cp_commit(); }

#pragma unroll
        for (int kk = 0; kk < FBK; kk += 8) {
            wmma::fragment<wmma::matrix_a, 16, 16, 8, wmma::precision::tf32, wmma::row_major> a[2];
            wmma::fragment<wmma::matrix_b, 16, 16, 8, wmma::precision::tf32, wmma::row_major> fg[2], fu[2];
#pragma unroll
            for (int im = 0; im < 2; im++) {
                wmma::load_matrix_sync(a[im], &sA[buf][wm * 32 + im * 16][kk], FBK + 4);
#pragma unroll
                for (int i = 0; i < a[im].num_elements; i++)
                    a[im].x[i] = wmma::__float_to_tf32(a[im].x[i]);
            }
#pragma unroll
            for (int in = 0; in < 2; in++) {
                wmma::load_matrix_sync(fg[in], &sBg[buf][kk][wn * 32 + in * 16], 64 + 4);
                wmma::load_matrix_sync(fu[in], &sBu[buf][kk][wn * 32 + in * 16], 64 + 4);
#pragma unroll
                for (int i = 0; i < fg[in].num_elements; i++) {
                    fg[in].x[i] = wmma::__float_to_tf32(fg[in].x[i]);
                    fu[in].x[i] = wmma::__float_to_tf32(fu[in].x[i]);
                }
            }
#pragma unroll
            for (int im = 0; im < 2; im++)
#pragma unroll
                for (int in = 0; in < 2; in++) {
                    wmma::mma_sync(accG[im][in], a[im], fg[in], accG[im][in]);
                    wmma::mma_sync(accU[im][in], a[im], fu[in], accU[im][in]);
                }
        }
        buf ^= 1;
    }

#pragma unroll
    for (int im = 0; im < 2; im++)
#pragma unroll
        for (int in = 0; in < 2; in++) {
#pragma unroll
            for (int i = 0; i < accG[im][in].num_elements; i++) {
                float g = accG[im][in].x[i];
                float u = accU[im][in].x[i];
                accG[im][in].x[i] = (g / (1.f + expf(-g))) * u;
            }
            size_t row = (size_t)base + blockIdx.x * BM + wm * 32 + im * 16;
            wmma::store_matrix_sync(g_h + row * INTER + n0 + wn * 32 + in * 16,
                                    accG[im][in], INTER, wmma::mem_row_major);
        }
#endif
}

__global__ void __launch_bounds__(256) k_gemm2_wm(const float* __restrict__ Wd)
{
#if !TC_OK
    int e = blockIdx.z;
    int cnt = g_cnt[e];
    if ((int)blockIdx.x * BM >= cnt) return;
    int base = g_off[e];
    int n0 = blockIdx.y * 64;

    __shared__ float sA[2][BM][FBK + 4];
    __shared__ float sB[2][FBK][64 + 4];

    int tid = threadIdx.x;
    int wid = tid >> 5;
    int wm = wid >> 1;
    int wn = wid & 1;

    int arow = tid >> 2;
    int acol = (tid & 3) << 2;
    const float* A = g_h + (size_t)(base + blockIdx.x * BM) * INTER;

    int brow = tid >> 4;
    int bcol = (tid & 15) << 2;
    const float* B = Wd + (size_t)e * INTER * HID + (size_t)brow * HID + n0 + bcol;

    wmma::fragment<wmma::accumulator, 16, 16, 8, float> acc[2][2];
#pragma unroll
    for (int im = 0; im < 2; im++)
#pragma unroll
        for (int in = 0; in < 2; in++)
            wmma::fill_fragment(acc[im][in], 0.f);

    auto load_tile = [&](int buf, int k0) {
#pragma unroll
        for (int p = 0; p < 2; p++) {
            int r = p * 64 + arow;
            cp16(smem_u32(&sA[buf][r][acol]), A + (size_t)r * INTER + k0 + acol);
        }
        cp16(smem_u32(&sB[buf][brow][bcol]), B + (size_t)k0 * HID);
    };

    load_tile(0, 0);
    cp_commit();

    int buf = 0;
    for (int k0 = 0; k0 < INTER; k0 += FBK) {
        cp_wait0();
        __syncthreads();
        if (k0 + FBK < INTER) { load_tile(buf ^ 1, k0 + FBK); cp_commit(); }

#pragma unroll
        for (int kk = 0; kk < FBK; kk += 8) {
            wmma::fragment<wmma::matrix_a, 16, 16, 8, wmma::precision::tf32, wmma::row_major> a[2];
            wmma::fragment<wmma::matrix_b, 16, 16, 8, wmma::precision::tf32, wmma::row_major> b[2];
#pragma unroll
            for (int im = 0; im < 2; im++) {
                wmma::load_matrix_sync(a[im], &sA[buf][wm * 32 + im * 16][kk], FBK + 4);
#pragma unroll
                for (int i = 0; i < a[im].num_elements; i++)
                    a[im].x[i] = wmma::__float_to_tf32(a[im].x[i]);
            }
#pragma unroll
            for (int in = 0; in < 2; in++) {
                wmma::load_matrix_sync(b[in], &sB[buf][kk][wn * 32 + in * 16], 64 + 4);
#pragma unroll
                for (int i = 0; i < b[in].num_elements; i++)
                    b[in].x[i] = wmma::__float_to_tf32(b[in].x[i]);
            }
#pragma unroll
            for (int im = 0; im < 2; im++)
#pragma unroll
                for (int in = 0; in < 2; in++)
                    wmma::mma_sync(acc[im][in], a[im], b[in], acc[im][in]);
        }
        buf ^= 1;
    }

#pragma unroll
    for (int im = 0; im < 2; im++)
#pragma unroll
        for (int in = 0; in < 2; in++) {
            size_t row = (size_t)base + blockIdx.x * BM + wm * 32 + im * 16;
            wmma::store_matrix_sync(g_down + row * HID + n0 + wn * 32 + in * 16,
                                    acc[im][in], HID, wmma::mem_row_major);
        }
#endif
}

// ---------------- launch ----------------
extern "C" void kernel_launch(void* const* d_in, const int* in_sizes, int n_in,
                              void* d_out, int out_size)
{
    const float* x      = (const float*)d_in[0];
    const float* logits = (const float*)d_in[1];
    const float* Wg     = (const float*)d_in[2];
    const float* Wu     = (const float*)d_in[3];
    const float* Wd     = (const float*)d_in[4];
    float* out = (float*)d_out;

    cudaFuncSetAttribute(k_gemm1_tc, cudaFuncAttributeMaxDynamicSharedMemorySize, 99328);
    cudaFuncSetAttribute(k_gemm2_tc, cudaFuncAttributeMaxDynamicSharedMemorySize, 99328);

    k_zero<<<1, 64>>>();
    k_route<<<(TOKENS + 127) / 128, 128>>>(logits);
    k_scan<<<1, 32>>>();
    k_scatter<<<(TOKENS * TOPK + 255) / 256, 256>>>();
    k_xround<<<(TOKENS * HID / 4 + 255) / 256, 256>>>(x);

    // tcgen05 path (no-op in non-'a' cubins)
    dim3 g1t(MT_MAX, INTER / 128, NEXP);
    k_gemm1_tc<<<g1t, 256, 99328>>>(Wg, Wu);
    dim3 g2t(MT_MAX, HID / 256, NEXP);
    k_gemm2_tc<<<g2t, 256, 99328>>>(Wd);

    // wmma fallback path (no-op in 'a' cubins)
    dim3 g1w(TOKENS / BM, INTER / 64, NEXP);
    k_gemm1_wm<<<g1w, 256>>>(x, Wg, Wu);
    dim3 g2w(TOKENS / BM, HID / 64, NEXP);
    k_gemm2_wm<<<g2w, 256>>>(Wd);

    int tot = TOKENS * (HID / 4);
    k_combine<<<(tot + 255) / 256, 256>>>(out);
}

// round 8
// speedup vs baseline: 3.9445x; 1.3634x over previous
#include <cuda_runtime.h>
#include <mma.h>
#include <math.h>
#include <stdint.h>

using namespace nvcuda;

// tcgen05 is only legal in arch-accelerated ('a') compile passes.
#if defined(__CUDA_ARCH_FEAT_SM103_ALL) || defined(__CUDA_ARCH_FEAT_SM100_ALL) || defined(__CUDA_ARCH_FEAT_SM101_ALL)
#define TC_OK 1
#else
#define TC_OK 0
#endif

#define TOKENS 8192
#define NEXP   64
#define TOPK   8
#define HID    2048
#define INTER  768
#define BM     128
#define MT_MAX 24

#define NT1 6      // gemm1 n-tiles (INTER/128)
#define KT1 64     // gemm1 k-chunks (HID/32)
#define NT2 8      // gemm2 n-tiles (HID/256)
#define KT2 24     // gemm2 k-chunks (INTER/32)

#define MAXROWS (TOKENS * TOPK + NEXP * BM)

// ---------------- scratch (static device memory) ----------------
__device__ float g_xr[(size_t)TOKENS * HID];       // tf32-rounded X
__device__ float g_h[(size_t)MAXROWS * INTER];     // silu(gate)*up
__device__ float g_down[(size_t)MAXROWS * HID];
// pre-rounded + pre-swizzled weight tile images (SW128 K-major)
__device__ float g_wg[(size_t)NEXP * NT1 * KT1 * 4096];   // 402MB
__device__ float g_wu[(size_t)NEXP * NT1 * KT1 * 4096];   // 402MB
__device__ float g_wd[(size_t)NEXP * NT2 * KT2 * 8192];   // 402MB
__device__ int   g_row_src[MAXROWS];
__device__ int   g_slot_of[TOKENS * TOPK];
__device__ float g_wt[TOKENS * TOPK];
__device__ int   g_expert[TOKENS * TOPK];
__device__ int   g_cnt[NEXP];
__device__ int   g_cursor[NEXP];
__device__ int   g_off[NEXP + 1];

// ---------------- common PTX helpers ----------------
__device__ __forceinline__ uint32_t smem_u32(const void* p) {
    return (uint32_t)__cvta_generic_to_shared(p);
}
__device__ __forceinline__ void cp16(uint32_t dst, const void* src) {
    asm volatile("cp.async.cg.shared.global [%0], [%1], 16;" :: "r"(dst), "l"(src));
}
__device__ __forceinline__ void cp16z(uint32_t dst, const void* src) {
    asm volatile("cp.async.cg.shared.global [%0], [%1], 16, 0;" :: "r"(dst), "l"(src));
}
__device__ __forceinline__ void cp_commit() { asm volatile("cp.async.commit_group;"); }
__device__ __forceinline__ void cp_wait0()  { asm volatile("cp.async.wait_group 0;"); }

__device__ __forceinline__ float tf32r(float x) {
    float r; asm("cvt.rna.tf32.f32 %0, %1;" : "=f"(r) : "f"(x)); return r;
}

// ---------------- small kernels ----------------
__global__ void k_zero() {
    int i = threadIdx.x;
    if (i < NEXP) { g_cnt[i] = 0; g_cursor[i] = 0; }
}

__global__ void k_route(const float* __restrict__ logits) {
    int t = blockIdx.x * blockDim.x + threadIdx.x;
    if (t >= TOKENS) return;
    float l[NEXP];
#pragma unroll
    for (int i = 0; i < NEXP; i++) l[i] = logits[t * NEXP + i];
    float vals[TOPK]; int ids[TOPK];
#pragma unroll
    for (int k = 0; k < TOPK; k++) {
        float best = -INFINITY; int bi = 0;
#pragma unroll
        for (int i = 0; i < NEXP; i++)
            if (l[i] > best) { best = l[i]; bi = i; }
        vals[k] = best; ids[k] = bi; l[bi] = -INFINITY;
    }
    float m = vals[0], s = 0.f, ex[TOPK];
#pragma unroll
    for (int k = 0; k < TOPK; k++) { ex[k] = expf(vals[k] - m); s += ex[k]; }
    float inv = 1.f / s;
#pragma unroll
    for (int k = 0; k < TOPK; k++) {
        g_wt[t * TOPK + k] = ex[k] * inv;
        g_expert[t * TOPK + k] = ids[k];
        atomicAdd(&g_cnt[ids[k]], 1);
    }
}

__global__ void k_scan() {
    if (threadIdx.x == 0) {
        int off = 0;
        for (int e = 0; e < NEXP; e++) {
            g_off[e] = off;
            off += ((g_cnt[e] + BM - 1) / BM) * BM;
        }
        g_off[NEXP] = off;
    }
}

__global__ void k_scatter() {
    int i = blockIdx.x * blockDim.x + threadIdx.x;
    if (i >= TOKENS * TOPK) return;
    int e = g_expert[i];
    int idx = atomicAdd(&g_cursor[e], 1);
    int slot = g_off[e] + idx;
    g_row_src[slot] = i / TOPK;
    g_slot_of[i] = slot;
}

__global__ void k_xround(const float* __restrict__ x) {
    size_t i = (size_t)blockIdx.x * blockDim.x + threadIdx.x;
    if (i >= (size_t)TOKENS * HID / 4) return;
    float4 v = ((const float4*)x)[i];
    v.x = tf32r(v.x); v.y = tf32r(v.y); v.z = tf32r(v.z); v.w = tf32r(v.w);
    ((float4*)g_xr)[i] = v;
}

// ---------------- weight prep: round to tf32-RN + transpose to K-major SW128 tiles ----------------
// gemm1 tile: [n=128 rows][k=32] -> 4096 floats, addr = n*128B + ((k*4)^((n&7)*16))
__global__ void __launch_bounds__(256) k_wprep1(const float* __restrict__ Wg,
                                                const float* __restrict__ Wu)
{
    int kc = blockIdx.x, nt = blockIdx.y, e = blockIdx.z;
    __shared__ float s[32][129];
    const float* srcs[2] = {
        Wg + (size_t)e * HID * INTER + (size_t)kc * 32 * INTER + nt * 128,
        Wu + (size_t)e * HID * INTER + (size_t)kc * 32 * INTER + nt * 128 };
    float* dsts[2] = {
        g_wg + (((size_t)e * NT1 + nt) * KT1 + kc) * 4096,
        g_wu + (((size_t)e * NT1 + nt) * KT1 + kc) * 4096 };

    for (int m = 0; m < 2; m++) {
        const float* src = srcs[m];
        float* dst = dsts[m];
#pragma unroll
        for (int j = 0; j < 4; j++) {
            int idx = threadIdx.x + j * 256;     // 0..1023
            int k = idx >> 5, c4 = idx & 31;     // 32 float4 per k-row
            float4 v = *(const float4*)(src + (size_t)k * INTER + c4 * 4);
            s[k][c4 * 4 + 0] = tf32r(v.x); s[k][c4 * 4 + 1] = tf32r(v.y);
            s[k][c4 * 4 + 2] = tf32r(v.z); s[k][c4 * 4 + 3] = tf32r(v.w);
        }
        __syncthreads();
#pragma unroll
        for (int j = 0; j < 4; j++) {
            int i = threadIdx.x + j * 256;       // 0..1023
            int n = i >> 3, c = i & 7;           // 8 16B-chunks per n-row
            float4 v = make_float4(s[c * 4 + 0][n], s[c * 4 + 1][n],
                                   s[c * 4 + 2][n], s[c * 4 + 3][n]);
            *(float4*)(dst + n * 32 + (((c * 16) ^ ((n & 7) * 16)) >> 2)) = v;
        }
        __syncthreads();
    }
}

// gemm2 tile: [n=256 rows][k=32] -> 8192 floats, same per-row formula
__global__ void __launch_bounds__(256) k_wprep2(const float* __restrict__ Wd)
{
    int kc = blockIdx.x, nt = blockIdx.y, e = blockIdx.z;
    __shared__ float s[32][257];
    const float* src = Wd + (size_t)e * INTER * HID + (size_t)kc * 32 * HID + nt * 256;
    float* dst = g_wd + (((size_t)e * NT2 + nt) * KT2 + kc) * 8192;
#pragma unroll
    for (int j = 0; j < 8; j++) {
        int idx = threadIdx.x + j * 256;         // 0..2047
        int k = idx >> 6, c4 = idx & 63;         // 64 float4 per k-row
        float4 v = *(const float4*)(src + (size_t)k * HID + c4 * 4);
        s[k][c4 * 4 + 0] = tf32r(v.x); s[k][c4 * 4 + 1] = tf32r(v.y);
        s[k][c4 * 4 + 2] = tf32r(v.z); s[k][c4 * 4 + 3] = tf32r(v.w);
    }
    __syncthreads();
#pragma unroll
    for (int j = 0; j < 8; j++) {
        int i = threadIdx.x + j * 256;           // 0..2047
        int n = i >> 3, c = i & 7;
        float4 v = make_float4(s[c * 4 + 0][n], s[c * 4 + 1][n],
                               s[c * 4 + 2][n], s[c * 4 + 3][n]);
        *(float4*)(dst + n * 32 + (((c * 16) ^ ((n & 7) * 16)) >> 2)) = v;
    }
}

__global__ void k_combine(float* __restrict__ out) {
    int idx = blockIdx.x * blockDim.x + threadIdx.x;
    const int VPT = HID / 4;
    if (idx >= TOKENS * VPT) return;
    int t = idx / VPT;
    int c = (idx % VPT) * 4;
    float4 acc = make_float4(0.f, 0.f, 0.f, 0.f);
#pragma unroll
    for (int k = 0; k < TOPK; k++) {
        int slot = g_slot_of[t * TOPK + k];
        float w = g_wt[t * TOPK + k];
        float4 v = *(const float4*)(g_down + (size_t)slot * HID + c);
        acc.x += w * v.x; acc.y += w * v.y; acc.z += w * v.z; acc.w += w * v.w;
    }
    *(float4*)(out + (size_t)t * HID + c) = acc;
}

// ============================================================================
// tcgen05 path (bodies only in 'a' passes)
// ============================================================================
#if TC_OK
__device__ __forceinline__ uint32_t elect_one() {
    uint32_t p;
    asm volatile("{\n\t.reg .pred p;\n\telect.sync _|p, 0xFFFFFFFF;\n\tselp.b32 %0, 1, 0, p;\n\t}" : "=r"(p));
    return p;
}

#define MBAR_INIT(addr, cnt) \
    asm volatile("mbarrier.init.shared.b64 [%0], %1;" :: "r"(addr), "r"(cnt) : "memory")
#define MBAR_WAIT(addr, parity) do { \
    uint32_t _m = (addr), _p = (parity); \
    asm volatile("{\n\t.reg .pred P;\n\tWL_%=:\n\t" \
        "mbarrier.try_wait.parity.acquire.cta.shared::cta.b64 P, [%0], %1, 0x989680;\n\t" \
        "@P bra.uni WD_%=;\n\tbra.uni WL_%=;\n\tWD_%=:\n\t}" \
        :: "r"(_m), "r"(_p) : "memory"); } while (0)

#define TC_ALLOC(dst, n)  asm volatile("tcgen05.alloc.cta_group::1.sync.aligned.shared::cta.b32 [%0], %1;" :: "r"(dst), "r"(n) : "memory")
#define TC_DEALLOC(t, n)  asm volatile("tcgen05.dealloc.cta_group::1.sync.aligned.b32 %0, %1;" :: "r"(t), "r"(n))
#define TC_RELINQ()       asm volatile("tcgen05.relinquish_alloc_permit.cta_group::1.sync.aligned;")
#define TC_COMMIT(mb)     asm volatile("tcgen05.commit.cta_group::1.mbarrier::arrive::one.shared::cluster.b64 [%0];" :: "r"(mb) : "memory")
#define TC_FENCE_AFTER()  asm volatile("tcgen05.fence::after_thread_sync;" ::: "memory")
#define TC_FENCE_BEFORE() asm volatile("tcgen05.fence::before_thread_sync;" ::: "memory")
#define TC_WAIT_LD()      asm volatile("tcgen05.wait::ld.sync.aligned;" ::: "memory")
#define FENCE_ASYNC()     asm volatile("fence.proxy.async.shared::cta;" ::: "memory")

#define TC_LD_X16(r, addr) \
    asm volatile("tcgen05.ld.sync.aligned.32x32b.x16.b32 " \
        "{%0,%1,%2,%3,%4,%5,%6,%7,%8,%9,%10,%11,%12,%13,%14,%15}, [%16];" \
        : "=r"((r)[0]), "=r"((r)[1]), "=r"((r)[2]), "=r"((r)[3]), \
          "=r"((r)[4]), "=r"((r)[5]), "=r"((r)[6]), "=r"((r)[7]), \
          "=r"((r)[8]), "=r"((r)[9]), "=r"((r)[10]), "=r"((r)[11]), \
          "=r"((r)[12]), "=r"((r)[13]), "=r"((r)[14]), "=r"((r)[15]) \
        : "r"(addr))

#define TC_LD_X32(r, addr) \
    asm volatile("tcgen05.ld.sync.aligned.32x32b.x32.b32 " \
        "{%0,%1,%2,%3,%4,%5,%6,%7,%8,%9,%10,%11,%12,%13,%14,%15," \
        "%16,%17,%18,%19,%20,%21,%22,%23,%24,%25,%26,%27,%28,%29,%30,%31}, [%32];" \
        : "=r"((r)[0]), "=r"((r)[1]), "=r"((r)[2]), "=r"((r)[3]), \
          "=r"((r)[4]), "=r"((r)[5]), "=r"((r)[6]), "=r"((r)[7]), \
          "=r"((r)[8]), "=r"((r)[9]), "=r"((r)[10]), "=r"((r)[11]), \
          "=r"((r)[12]), "=r"((r)[13]), "=r"((r)[14]), "=r"((r)[15]), \
          "=r"((r)[16]), "=r"((r)[17]), "=r"((r)[18]), "=r"((r)[19]), \
          "=r"((r)[20]), "=r"((r)[21]), "=r"((r)[22]), "=r"((r)[23]), \
          "=r"((r)[24]), "=r"((r)[25]), "=r"((r)[26]), "=r"((r)[27]), \
          "=r"((r)[28]), "=r"((r)[29]), "=r"((r)[30]), "=r"((r)[31]) \
        : "r"(addr))

__device__ __forceinline__ void mma_tf32(uint32_t d_tmem, uint64_t a_desc, uint64_t b_desc,
                                         uint32_t idesc, bool acc) {
    uint32_t en = acc ? 1u : 0u;
    asm volatile("{\n\t.reg .pred p;\n\tsetp.ne.u32 p, %5, 0;\n\t"
                 "tcgen05.mma.cta_group::1.kind::tf32 [%0], %1, %2, %3, {%4, %4, %4, %4}, p;\n\t}"
                 :: "r"(d_tmem), "l"(a_desc), "l"(b_desc), "r"(idesc), "r"(0u), "r"(en)
                 : "memory");
}

__device__ __forceinline__ uint64_t mkdesc(uint32_t addr) {
    const uint64_t base = (2ull << 61) | (1ull << 46) | (64ull << 32) | (1ull << 16);
    return base | ((uint64_t)(addr >> 4) & 0x3FFF);
}

#define IDESC_N128 ((1u << 4) | (2u << 7) | (2u << 10) | (16u << 17) | (8u << 24))
#define IDESC_N256 ((1u << 4) | (2u << 7) | (2u << 10) | (32u << 17) | (8u << 24))
#endif  // TC_OK

// ---------------- GEMM1 tcgen05: gate+up, BM=128, BN=128 (x2 mats), BK=32 ----------------
__global__ void __launch_bounds__(256, 2) k_gemm1_tc(const float* __restrict__ WgU,
                                                     const float* __restrict__ WuU)
{
#if TC_OK
    int e = blockIdx.z;
    int cnt = g_cnt[e];
    int mtile = blockIdx.x;
    if (mtile * BM >= cnt) return;
    int base = g_off[e];
    int nt = blockIdx.y;
    int n0 = nt * 128;

    extern __shared__ char dsm[];
    __shared__ uint32_t s_tmem;
    __shared__ uint64_t s_mbar[2];
    uint32_t sbase = (smem_u32(dsm) + 1023) & ~1023u;
    uint32_t sA[2]  = { sbase,          sbase + 16384 };
    uint32_t sBg[2] = { sbase + 32768,  sbase + 49152 };
    uint32_t sBu[2] = { sbase + 65536,  sbase + 81920 };

    int tid = threadIdx.x, wid = tid >> 5, lane = tid & 31;

    if (tid == 0) {
        MBAR_INIT(smem_u32(&s_mbar[0]), 1);
        MBAR_INIT(smem_u32(&s_mbar[1]), 1);
    }
    if (wid == 0) { TC_ALLOC(smem_u32(&s_tmem), 256); TC_RELINQ(); }
    __syncthreads();
    uint32_t tmem = s_tmem;

    // A gather map
    int c8 = tid & 7;
    const float* asrc[4];
    uint32_t adst[4];
#pragma unroll
    for (int p = 0; p < 4; p++) {
        int r = (tid >> 3) + p * 32;
        int gr = mtile * BM + r;
        int s = (gr < cnt) ? g_row_src[base + gr] : -1;
        asrc[p] = (s >= 0) ? (g_xr + (size_t)s * HID + c8 * 4) : nullptr;
        adst[p] = (uint32_t)(r * 128 + ((c8 ^ (r & 7)) * 16));
    }

    // pre-baked tile streams (contiguous 16KB per k-chunk)
    const float* tg = g_wg + (((size_t)e * NT1 + nt) * KT1) * 4096 + tid * 16;
    const float* tu = g_wu + (((size_t)e * NT1 + nt) * KT1) * 4096 + tid * 16;
    uint32_t bdst = (uint32_t)(tid * 64);

    int ph[2] = { 0, 0 };
    const int KT = KT1;   // 64

    for (int it = 0; it < KT; it++) {
        int b = it & 1;
        if (it >= 2) { MBAR_WAIT(smem_u32(&s_mbar[b]), ph[b]); ph[b] ^= 1; }
        int k0 = it * 32;

#pragma unroll
        for (int p = 0; p < 4; p++) {
            if (asrc[p]) cp16(sA[b] + adst[p], asrc[p] + k0);
            else         cp16z(sA[b] + adst[p], g_xr);
        }
        const float* pg = tg + (size_t)it * 4096;
        const float* pu = tu + (size_t)it * 4096;
#pragma unroll
        for (int j = 0; j < 4; j++) {
            cp16(sBg[b] + bdst + j * 16, pg + j * 4);
            cp16(sBu[b] + bdst + j * 16, pu + j * 4);
        }
        cp_commit();
        cp_wait0();
        __syncthreads();

        if (wid == 0) {
            FENCE_ASYNC();
            if (elect_one()) {
                uint64_t da = mkdesc(sA[b]);
                uint64_t dg = mkdesc(sBg[b]);
                uint64_t du = mkdesc(sBu[b]);
#pragma unroll
                for (int ks = 0; ks < 4; ks++) {
                    bool acc = !(it == 0 && ks == 0);
                    mma_tf32(tmem,       da + 2 * ks, dg + 2 * ks, IDESC_N128, acc);
                    mma_tf32(tmem + 128, da + 2 * ks, du + 2 * ks, IDESC_N128, acc);
                }
                TC_COMMIT(smem_u32(&s_mbar[b]));
            }
        }
    }

    int bl = (KT - 1) & 1;
    MBAR_WAIT(smem_u32(&s_mbar[bl]), ph[bl]);
    TC_FENCE_AFTER();

    if (wid < 4) {
        int m = wid * 32 + lane;
        float* dst = g_h + (size_t)(base + mtile * BM + m) * INTER + n0;
#pragma unroll
        for (int c0 = 0; c0 < 128; c0 += 16) {
            uint32_t rg[16], ru[16];
            TC_LD_X16(rg, tmem + c0);
            TC_LD_X16(ru, tmem + 128 + c0);
            TC_WAIT_LD();
#pragma unroll
            for (int j = 0; j < 16; j++) {
                float g = __uint_as_float(rg[j]);
                float u = __uint_as_float(ru[j]);
                float h = (g / (1.f + __expf(-g))) * u;
                rg[j] = __float_as_uint(tf32r(h));
            }
#pragma unroll
            for (int j = 0; j < 16; j += 4)
                *(uint4*)(dst + c0 + j) = make_uint4(rg[j], rg[j+1], rg[j+2], rg[j+3]);
        }
        TC_FENCE_BEFORE();
    }
    __syncthreads();
    if (wid == 0) TC_DEALLOC(tmem, 256);
#endif
}

// ---------------- GEMM2 tcgen05: down proj, BM=128, BN=256, BK=32 ----------------
__global__ void __launch_bounds__(256, 2) k_gemm2_tc(const float* __restrict__ WdU)
{
#if TC_OK
    int e = blockIdx.z;
    int cnt = g_cnt[e];
    int mtile = blockIdx.x;
    if (mtile * BM >= cnt) return;
    int base = g_off[e];
    int nt = blockIdx.y;
    int n0 = nt * 256;

    extern __shared__ char dsm[];
    __shared__ uint32_t s_tmem;
    __shared__ uint64_t s_mbar[2];
    uint32_t sbase = (smem_u32(dsm) + 1023) & ~1023u;
    uint32_t sA[2] = { sbase,         sbase + 16384 };
    uint32_t sB[2] = { sbase + 32768, sbase + 65536 };

    int tid = threadIdx.x, wid = tid >> 5, lane = tid & 31;

    if (tid == 0) {
        MBAR_INIT(smem_u32(&s_mbar[0]), 1);
        MBAR_INIT(smem_u32(&s_mbar[1]), 1);
    }
    if (wid == 0) { TC_ALLOC(smem_u32(&s_tmem), 256); TC_RELINQ(); }
    __syncthreads();
    uint32_t tmem = s_tmem;

    int c8 = tid & 7;
    const float* asrc[4];
    uint32_t adst[4];
#pragma unroll
    for (int p = 0; p < 4; p++) {
        int r = (tid >> 3) + p * 32;
        asrc[p] = g_h + (size_t)(base + mtile * BM + r) * INTER + c8 * 4;
        adst[p] = (uint32_t)(r * 128 + ((c8 ^ (r & 7)) * 16));
    }

    const float* td = g_wd + (((size_t)e * NT2 + nt) * KT2) * 8192 + tid * 32;
    uint32_t bdst = (uint32_t)(tid * 128);

    int ph[2] = { 0, 0 };
    const int KT = KT2;   // 24

    for (int it = 0; it < KT; it++) {
        int b = it & 1;
        if (it >= 2) { MBAR_WAIT(smem_u32(&s_mbar[b]), ph[b]); ph[b] ^= 1; }
        int k0 = it * 32;

#pragma unroll
        for (int p = 0; p < 4; p++)
            cp16(sA[b] + adst[p], asrc[p] + k0);
        const float* pw = td + (size_t)it * 8192;
#pragma unroll
        for (int j = 0; j < 8; j++)
            cp16(sB[b] + bdst + j * 16, pw + j * 4);
        cp_commit();
        cp_wait0();
        __syncthreads();

        if (wid == 0) {
            FENCE_ASYNC();
            if (elect_one()) {
                uint64_t da = mkdesc(sA[b]);
                uint64_t db = mkdesc(sB[b]);
#pragma unroll
                for (int ks = 0; ks < 4; ks++) {
                    bool acc = !(it == 0 && ks == 0);
                    mma_tf32(tmem, da + 2 * ks, db + 2 * ks, IDESC_N256, acc);
                }
                TC_COMMIT(smem_u32(&s_mbar[b]));
            }
        }
    }

    int bl = (KT - 1) & 1;
    MBAR_WAIT(smem_u32(&s_mbar[bl]), ph[bl]);
    TC_FENCE_AFTER();

    if (wid < 4) {
        int m = wid * 32 + lane;
        float* dst = g_down + (size_t)(base + mtile * BM + m) * HID + n0;
#pragma unroll
        for (int c0 = 0; c0 < 256; c0 += 32) {
            uint32_t r[32];
            TC_LD_X32(r, tmem + c0);
            TC_WAIT_LD();
#pragma unroll
            for (int j = 0; j < 32; j += 4)
                *(uint4*)(dst + c0 + j) = make_uint4(r[j], r[j+1], r[j+2], r[j+3]);
        }
        TC_FENCE_BEFORE();
    }
    __syncthreads();
    if (wid == 0) TC_DEALLOC(tmem, 256);
#endif
}

// ============================================================================
// wmma fallback path (bodies only in non-'a' device passes)
// ============================================================================
#define FBK 16

__global__ void __launch_bounds__(256) k_gemm1_wm(
    const float* __restrict__ x,
    const float* __restrict__ Wg,
    const float* __restrict__ Wu)
{
#if !TC_OK
    int e = blockIdx.z;
    int cnt = g_cnt[e];
    if ((int)blockIdx.x * BM >= cnt) return;
    int base = g_off[e];
    int n0 = blockIdx.y * 64;

    __shared__ float sA [2][BM][FBK + 4];
    __shared__ float sBg[2][FBK][64 + 4];
    __shared__ float sBu[2][FBK][64 + 4];

    int tid = threadIdx.x;
    int wid = tid >> 5;
    int wm = wid >> 1;
    int wn = wid & 1;

    int arow = tid >> 2;
    int acol = (tid & 3) << 2;
    const float* aptr[2];
#pragma unroll
    for (int p = 0; p < 2; p++) {
        int r = blockIdx.x * BM + p * 64 + arow;
        int s = (r < cnt) ? g_row_src[base + r] : -1;
        aptr[p] = (s >= 0) ? (x + (size_t)s * HID + acol) : nullptr;
    }
    int brow = tid >> 4;
    int bcol = (tid & 15) << 2;
    const float* bg = Wg + (size_t)e * HID * INTER + (size_t)brow * INTER + n0 + bcol;
    const float* bu = Wu + (size_t)e * HID * INTER + (size_t)brow * INTER + n0 + bcol;

    wmma::fragment<wmma::accumulator, 16, 16, 8, float> accG[2][2], accU[2][2];
#pragma unroll
    for (int im = 0; im < 2; im++)
#pragma unroll
        for (int in = 0; in < 2; in++) {
            wmma::fill_fragment(accG[im][in], 0.f);
            wmma::fill_fragment(accU[im][in], 0.f);
        }

    auto load_tile = [&](int buf, int k0) {
#pragma unroll
        for (int p = 0; p < 2; p++) {
            uint32_t d = smem_u32(&sA[buf][p * 64 + arow][acol]);
            if (aptr[p]) cp16(d, aptr[p] + k0);
            else         cp16z(d, x);
        }
        cp16(smem_u32(&sBg[buf][brow][bcol]), bg + (size_t)k0 * INTER);
        cp16(smem_u32(&sBu[buf][brow][bcol]), bu + (size_t)k0 * INTER);
    };

    load_tile(0, 0);
    cp_commit();

    int buf = 0;
    for (int k0 = 0; k0 < HID; k0 += FBK) {
        cp_wait0();
        __syncthreads();
        if (k0 + FBK < HID) { load_tile(buf ^ 1, k0 + FBK); cp_commit(); }

#pragma unroll
        for (int kk = 0; kk < FBK; kk += 8) {
            wmma::fragment<wmma::matrix_a, 16, 16, 8, wmma::precision::tf32, wmma::row_major> a[2];
            wmma::fragment<wmma::matrix_b, 16, 16, 8, wmma::precision::tf32, wmma::row_major> fg[2], fu[2];
#pragma unroll
            for (int im = 0; im < 2; im++) {
                wmma::load_matrix_sync(a[im], &sA[buf][wm * 32 + im * 16][kk], FBK + 4);
#pragma unroll
                for (int i = 0; i < a[im].num_elements; i++)
                    a[im].x[i] = wmma::__float_to_tf32(a[im].x[i]);
            }
#pragma unroll
            for (int in = 0; in < 2; in++) {
                wmma::load_matrix_sync(fg[in], &sBg[buf][kk][wn * 32 + in * 16], 64 + 4);
                wmma::load_matrix_sync(fu[in], &sBu[buf][kk][wn * 32 + in * 16], 64 + 4);
#pragma unroll
                for (int i = 0; i < fg[in].num_elements; i++) {
                    fg[in].x[i] = wmma::__float_to_tf32(fg[in].x[i]);
                    fu[in].x[i] = wmma::__float_to_tf32(fu[in].x[i]);
                }
            }
#pragma unroll
            for (int im = 0; im < 2; im++)
#pragma unroll
                for (int in = 0; in < 2; in++) {
                    wmma::mma_sync(accG[im][in], a[im], fg[in], accG[im][in]);
                    wmma::mma_sync(accU[im][in], a[im], fu[in], accU[im][in]);
                }
        }
        buf ^= 1;
    }

#pragma unroll
    for (int im = 0; im < 2; im++)
#pragma unroll
        for (int in = 0; in < 2; in++) {
#pragma unroll
            for (int i = 0; i < accG[im][in].num_elements; i++) {
                float g = accG[im][in].x[i];
                float u = accU[im][in].x[i];
                accG[im][in].x[i] = (g / (1.f + expf(-g))) * u;
            }
            size_t row = (size_t)base + blockIdx.x * BM + wm * 32 + im * 16;
            wmma::store_matrix_sync(g_h + row * INTER + n0 + wn * 32 + in * 16,
                                    accG[im][in], INTER, wmma::mem_row_major);
        }
#endif
}

__global__ void __launch_bounds__(256) k_gemm2_wm(const float* __restrict__ Wd)
{
#if !TC_OK
    int e = blockIdx.z;
    int cnt = g_cnt[e];
    if ((int)blockIdx.x * BM >= cnt) return;
    int base = g_off[e];
    int n0 = blockIdx.y * 64;

    __shared__ float sA[2][BM][FBK + 4];
    __shared__ float sB[2][FBK][64 + 4];

    int tid = threadIdx.x;
    int wid = tid >> 5;
    int wm = wid >> 1;
    int wn = wid & 1;

    int arow = tid >> 2;
    int acol = (tid & 3) << 2;
    const float* A = g_h + (size_t)(base + blockIdx.x * BM) * INTER;

    int brow = tid >> 4;
    int bcol = (tid & 15) << 2;
    const float* B = Wd + (size_t)e * INTER * HID + (size_t)brow * HID + n0 + bcol;

    wmma::fragment<wmma::accumulator, 16, 16, 8, float> acc[2][2];
#pragma unroll
    for (int im = 0; im < 2; im++)
#pragma unroll
        for (int in = 0; in < 2; in++)
            wmma::fill_fragment(acc[im][in], 0.f);

    auto load_tile = [&](int buf, int k0) {
#pragma unroll
        for (int p = 0; p < 2; p++) {
            int r = p * 64 + arow;
            cp16(smem_u32(&sA[buf][r][acol]), A + (size_t)r * INTER + k0 + acol);
        }
        cp16(smem_u32(&sB[buf][brow][bcol]), B + (size_t)k0 * HID);
    };

    load_tile(0, 0);
    cp_commit();

    int buf = 0;
    for (int k0 = 0; k0 < INTER; k0 += FBK) {
        cp_wait0();
        __syncthreads();
        if (k0 + FBK < INTER) { load_tile(buf ^ 1, k0 + FBK); cp_commit(); }

#pragma unroll
        for (int kk = 0; kk < FBK; kk += 8) {
            wmma::fragment<wmma::matrix_a, 16, 16, 8, wmma::precision::tf32, wmma::row_major> a[2];
            wmma::fragment<wmma::matrix_b, 16, 16, 8, wmma::precision::tf32, wmma::row_major> b[2];
#pragma unroll
            for (int im = 0; im < 2; im++) {
                wmma::load_matrix_sync(a[im], &sA[buf][wm * 32 + im * 16][kk], FBK + 4);
#pragma unroll
                for (int i = 0; i < a[im].num_elements; i++)
                    a[im].x[i] = wmma::__float_to_tf32(a[im].x[i]);
            }
#pragma unroll
            for (int in = 0; in < 2; in++) {
                wmma::load_matrix_sync(b[in], &sB[buf][kk][wn * 32 + in * 16], 64 + 4);
#pragma unroll
                for (int i = 0; i < b[in].num_elements; i++)
                    b[in].x[i] = wmma::__float_to_tf32(b[in].x[i]);
            }
#pragma unroll
            for (int im = 0; im < 2; im++)
#pragma unroll
                for (int in = 0; in < 2; in++)
                    wmma::mma_sync(acc[im][in], a[im], b[in], acc[im][in]);
        }
        buf ^= 1;
    }

#pragma unroll
    for (int im = 0; im < 2; im++)
#pragma unroll
        for (int in = 0; in < 2; in++) {
            size_t row = (size_t)base + blockIdx.x * BM + wm * 32 + im * 16;
            wmma::store_matrix_sync(g_down + row * HID + n0 + wn * 32 + in * 16,
                                    acc[im][in], HID, wmma::mem_row_major);
        }
#endif
}

// ---------------- launch ----------------
extern "C" void kernel_launch(void* const* d_in, const int* in_sizes, int n_in,
                              void* d_out, int out_size)
{
    const float* x      = (const float*)d_in[0];
    const float* logits = (const float*)d_in[1];
    const float* Wg     = (const float*)d_in[2];
    const float* Wu     = (const float*)d_in[3];
    const float* Wd     = (const float*)d_in[4];
    float* out = (float*)d_out;

    cudaFuncSetAttribute(k_gemm1_tc, cudaFuncAttributeMaxDynamicSharedMemorySize, 99328);
    cudaFuncSetAttribute(k_gemm2_tc, cudaFuncAttributeMaxDynamicSharedMemorySize, 99328);

    k_zero<<<1, 64>>>();
    k_route<<<(TOKENS + 127) / 128, 128>>>(logits);
    k_scan<<<1, 32>>>();
    k_scatter<<<(TOKENS * TOPK + 255) / 256, 256>>>();
    k_xround<<<(TOKENS * HID / 4 + 255) / 256, 256>>>(x);

    // weight prep: tf32-RN round + K-major SW128 tile bake
    dim3 gp1(KT1, NT1, NEXP);
    k_wprep1<<<gp1, 256>>>(Wg, Wu);
    dim3 gp2(KT2, NT2, NEXP);
    k_wprep2<<<gp2, 256>>>(Wd);

    // tcgen05 path (no-op in non-'a' cubins)
    dim3 g1t(MT_MAX, NT1, NEXP);
    k_gemm1_tc<<<g1t, 256, 99328>>>(Wg, Wu);
    dim3 g2t(MT_MAX, NT2, NEXP);
    k_gemm2_tc<<<g2t, 256, 99328>>>(Wd);

    // wmma fallback path (no-op in 'a' cubins)
    dim3 g1w(TOKENS / BM, INTER / 64, NEXP);
    k_gemm1_wm<<<g1w, 256>>>(x, Wg, Wu);
    dim3 g2w(TOKENS / BM, HID / 64, NEXP);
    k_gemm2_wm<<<g2w, 256>>>(Wd);

    int tot = TOKENS * (HID / 4);
    k_combine<<<(tot + 255) / 256, 256>>>(out);
}